// round 8
// baseline (speedup 1.0000x reference)
#include <cuda_runtime.h>
#include <cuda_bf16.h>
#include <cstdint>
#include <cstddef>

#define N_JOBS 100000
#define N_MACH 10000
#define DIM 128
#define KDIM 256
#define BM 64
#define LN_EPS 1e-5f
#define MAX_EDGES 1600000

#define JOB_TILES ((N_JOBS + BM - 1) / BM)    // 1563
#define MACH_TILES ((N_MACH + BM - 1) / BM)   // 157

#define SCAN_CHUNK 512
#define JB ((N_JOBS + SCAN_CHUNK - 1) / SCAN_CHUNK)   // 196
#define MB ((N_MACH + SCAN_CHUNK - 1) / SCAN_CHUNK)   // 20

// Scratch device globals (no allocations allowed): CSR ~14MB, agg ~56MB, bf16 tables ~28MB.
__device__ int g_job_off[N_JOBS + 1];
__device__ int g_mach_off[N_MACH + 1];
__device__ int g_job_cur[N_JOBS];
__device__ int g_mach_cur[N_MACH];
__device__ int g_job_nbr[MAX_EDGES];
__device__ int g_mach_nbr[MAX_EDGES];
__device__ int g_bsum[JB + MB];
__device__ __align__(256) float g_job_agg[(size_t)N_JOBS * DIM];
__device__ __align__(256) float g_mach_agg[(size_t)N_MACH * DIM];
__device__ __align__(256) __nv_bfloat16 g_job_bf[(size_t)N_JOBS * DIM];
__device__ __align__(256) __nv_bfloat16 g_mach_bf[(size_t)N_MACH * DIM];

__global__ void zero_cnt_kernel() {
    int i = blockIdx.x * blockDim.x + threadIdx.x;
    int stride = gridDim.x * blockDim.x;
    for (int t = i; t < N_JOBS; t += stride) g_job_cur[t] = 0;
    for (int t = i; t < N_MACH; t += stride) g_mach_cur[t] = 0;
}

// fp32 -> bf16 copies of both feature tables (halves gather bytes in agg).
__global__ void convert_bf16_kernel(const float* __restrict__ job_h,
                                    const float* __restrict__ machine_h) {
    int i = blockIdx.x * blockDim.x + threadIdx.x;
    int stride = gridDim.x * blockDim.x;
    const int nj = N_JOBS * DIM / 4, nm = N_MACH * DIM / 4;
    for (int t = i; t < nj; t += stride) {
        float4 v = ((const float4*)job_h)[t];
        __nv_bfloat162 lo = __floats2bfloat162_rn(v.x, v.y);
        __nv_bfloat162 hi = __floats2bfloat162_rn(v.z, v.w);
        uint2 p; p.x = *(unsigned*)&lo; p.y = *(unsigned*)&hi;
        ((uint2*)g_job_bf)[t] = p;
    }
    for (int t = i; t < nm; t += stride) {
        float4 v = ((const float4*)machine_h)[t];
        __nv_bfloat162 lo = __floats2bfloat162_rn(v.x, v.y);
        __nv_bfloat162 hi = __floats2bfloat162_rn(v.z, v.w);
        uint2 p; p.x = *(unsigned*)&lo; p.y = *(unsigned*)&hi;
        ((uint2*)g_mach_bf)[t] = p;
    }
}

// 4 edges per iteration -> 8 independent atomics in flight.
__global__ void hist_kernel(const int* __restrict__ job_idx,
                            const int* __restrict__ mach_idx, int n_edges) {
    int i = blockIdx.x * blockDim.x + threadIdx.x;
    int stride = gridDim.x * blockDim.x;
    int n4 = n_edges >> 2;
    const int4* j4 = (const int4*)job_idx;
    const int4* m4 = (const int4*)mach_idx;
    for (int e = i; e < n4; e += stride) {
        int4 a = __ldg(j4 + e);
        int4 b = __ldg(m4 + e);
        atomicAdd(&g_job_cur[a.x], 1);  atomicAdd(&g_job_cur[a.y], 1);
        atomicAdd(&g_job_cur[a.z], 1);  atomicAdd(&g_job_cur[a.w], 1);
        atomicAdd(&g_mach_cur[b.x], 1); atomicAdd(&g_mach_cur[b.y], 1);
        atomicAdd(&g_mach_cur[b.z], 1); atomicAdd(&g_mach_cur[b.w], 1);
    }
    int rem = n_edges & 3;
    if (i < rem) {
        int e = n4 * 4 + i;
        atomicAdd(&g_job_cur[__ldg(job_idx + e)], 1);
        atomicAdd(&g_mach_cur[__ldg(mach_idx + e)], 1);
    }
}

// Pass A: per-block (512 elems) local exclusive scan into off[], block total -> g_bsum.
__global__ void scanA_kernel() {
    bool is_mach = blockIdx.x >= JB;
    const int* cnt = is_mach ? g_mach_cur : g_job_cur;
    int* off = is_mach ? g_mach_off : g_job_off;
    int n    = is_mach ? N_MACH : N_JOBS;
    int b    = is_mach ? (blockIdx.x - JB) : blockIdx.x;

    int tid = threadIdx.x;            // 256 threads, 2 elems each
    int lane = tid & 31, wid = tid >> 5;
    int idx = b * SCAN_CHUNK + tid * 2;
    int v0 = (idx     < n) ? cnt[idx]     : 0;
    int v1 = (idx + 1 < n) ? cnt[idx + 1] : 0;
    int tsum = v0 + v1;
    int incl = tsum;
    #pragma unroll
    for (int o = 1; o < 32; o <<= 1) {
        int t = __shfl_up_sync(0xffffffffu, incl, o);
        if (lane >= o) incl += t;
    }
    __shared__ int wsum[8];
    if (lane == 31) wsum[wid] = incl;
    __syncthreads();
    if (tid < 8) {
        int ws = wsum[tid];
        #pragma unroll
        for (int o = 1; o < 8; o <<= 1) {
            int t = __shfl_up_sync(0xffu, ws, o);
            if (tid >= o) ws += t;
        }
        wsum[tid] = ws;
    }
    __syncthreads();
    int base = (wid == 0 ? 0 : wsum[wid - 1]) + (incl - tsum);
    if (idx     < n) off[idx]     = base;
    if (idx + 1 < n) off[idx + 1] = base + v0;
    if (tid == 255) g_bsum[blockIdx.x] = wsum[7];
}

// Pass B: one block exclusive-scans g_bsum for jobs [0,JB) and machines [JB,JB+MB).
__global__ void scanB_kernel(int n_edges) {
    int tid = threadIdx.x;   // 256 >= max(JB, MB)
    int lane = tid & 31, wid = tid >> 5;
    __shared__ int wsum[8];
    #pragma unroll
    for (int seg = 0; seg < 2; seg++) {
        int n = seg ? MB : JB;
        int o0 = seg ? JB : 0;
        int v = (tid < n) ? g_bsum[o0 + tid] : 0;
        int incl = v;
        #pragma unroll
        for (int o = 1; o < 32; o <<= 1) {
            int t = __shfl_up_sync(0xffffffffu, incl, o);
            if (lane >= o) incl += t;
        }
        if (lane == 31) wsum[wid] = incl;
        __syncthreads();
        if (tid < 8) {
            int ws = wsum[tid];
            #pragma unroll
            for (int o = 1; o < 8; o <<= 1) {
                int t = __shfl_up_sync(0xffu, ws, o);
                if (tid >= o) ws += t;
            }
            wsum[tid] = ws;
        }
        __syncthreads();
        int excl = (wid == 0 ? 0 : wsum[wid - 1]) + (incl - v);
        if (tid < n) g_bsum[o0 + tid] = excl;
        __syncthreads();
    }
    if (tid == 0) { g_job_off[N_JOBS] = n_edges; g_mach_off[N_MACH] = n_edges; }
}

// Pass C: add block bases, copy off -> cur (fill cursors).
__global__ void scanC_kernel() {
    bool is_mach = blockIdx.x >= JB;
    int* off = is_mach ? g_mach_off : g_job_off;
    int* cur = is_mach ? g_mach_cur : g_job_cur;
    int n    = is_mach ? N_MACH : N_JOBS;
    int b    = is_mach ? (blockIdx.x - JB) : blockIdx.x;
    int base = g_bsum[blockIdx.x];
    int idx = b * SCAN_CHUNK + threadIdx.x * 2;
    if (idx < n)     { int v = off[idx]     + base; off[idx]     = v; cur[idx]     = v; }
    if (idx + 1 < n) { int v = off[idx + 1] + base; off[idx + 1] = v; cur[idx + 1] = v; }
}

// 4 edges per iteration -> 8 independent atomic+store chains.
__global__ void fill_kernel(const int* __restrict__ job_idx,
                            const int* __restrict__ mach_idx, int n_edges) {
    int i = blockIdx.x * blockDim.x + threadIdx.x;
    int stride = gridDim.x * blockDim.x;
    int n4 = n_edges >> 2;
    const int4* j4 = (const int4*)job_idx;
    const int4* m4 = (const int4*)mach_idx;
    for (int e = i; e < n4; e += stride) {
        int4 a = __ldg(j4 + e);
        int4 b = __ldg(m4 + e);
        int p0 = atomicAdd(&g_job_cur[a.x], 1);
        int p1 = atomicAdd(&g_job_cur[a.y], 1);
        int p2 = atomicAdd(&g_job_cur[a.z], 1);
        int p3 = atomicAdd(&g_job_cur[a.w], 1);
        int q0 = atomicAdd(&g_mach_cur[b.x], 1);
        int q1 = atomicAdd(&g_mach_cur[b.y], 1);
        int q2 = atomicAdd(&g_mach_cur[b.z], 1);
        int q3 = atomicAdd(&g_mach_cur[b.w], 1);
        g_job_nbr[p0] = b.x;  g_job_nbr[p1] = b.y;
        g_job_nbr[p2] = b.z;  g_job_nbr[p3] = b.w;
        g_mach_nbr[q0] = a.x; g_mach_nbr[q1] = a.y;
        g_mach_nbr[q2] = a.z; g_mach_nbr[q3] = a.w;
    }
    int rem = n_edges & 3;
    if (i < rem) {
        int e = n4 * 4 + i;
        int j = __ldg(job_idx + e);
        int m = __ldg(mach_idx + e);
        g_job_nbr[atomicAdd(&g_job_cur[j], 1)] = m;
        g_mach_nbr[atomicAdd(&g_mach_cur[m], 1)] = j;
    }
}

// Warp per row: CSR gather-mean over bf16 tables (256B/row), fp32 accumulate.
// Lane owns 4 consecutive bf16 (8B). Unroll-4 -> 4 independent gathers in flight.
__global__ __launch_bounds__(256) void agg_kernel() {
    int gw = (blockIdx.x * blockDim.x + threadIdx.x) >> 5;
    if (gw >= N_JOBS + N_MACH) return;
    int lane = threadIdx.x & 31;
    const int* off; const int* nbr; const __nv_bfloat16* src; float* dst; int r;
    if (gw < N_JOBS) { r = gw;          off = g_job_off;  nbr = g_job_nbr;  src = g_mach_bf; dst = g_job_agg; }
    else             { r = gw - N_JOBS; off = g_mach_off; nbr = g_mach_nbr; src = g_job_bf;  dst = g_mach_agg; }
    int s = off[r], e = off[r + 1];
    int c = lane << 2;                 // 4 bf16 per lane
    float4 a0 = make_float4(0.f, 0.f, 0.f, 0.f);
    float4 a1 = a0, a2 = a0, a3 = a0;
    int p = s;
    for (; p + 4 <= e; p += 4) {
        int n0 = __ldg(nbr + p);
        int n1 = __ldg(nbr + p + 1);
        int n2 = __ldg(nbr + p + 2);
        int n3 = __ldg(nbr + p + 3);
        uint2 u0 = *(const uint2*)(src + (size_t)n0 * DIM + c);
        uint2 u1 = *(const uint2*)(src + (size_t)n1 * DIM + c);
        uint2 u2 = *(const uint2*)(src + (size_t)n2 * DIM + c);
        uint2 u3 = *(const uint2*)(src + (size_t)n3 * DIM + c);
        float2 f;
        f = __bfloat1622float2(*(__nv_bfloat162*)&u0.x); a0.x += f.x; a0.y += f.y;
        f = __bfloat1622float2(*(__nv_bfloat162*)&u0.y); a0.z += f.x; a0.w += f.y;
        f = __bfloat1622float2(*(__nv_bfloat162*)&u1.x); a1.x += f.x; a1.y += f.y;
        f = __bfloat1622float2(*(__nv_bfloat162*)&u1.y); a1.z += f.x; a1.w += f.y;
        f = __bfloat1622float2(*(__nv_bfloat162*)&u2.x); a2.x += f.x; a2.y += f.y;
        f = __bfloat1622float2(*(__nv_bfloat162*)&u2.y); a2.z += f.x; a2.w += f.y;
        f = __bfloat1622float2(*(__nv_bfloat162*)&u3.x); a3.x += f.x; a3.y += f.y;
        f = __bfloat1622float2(*(__nv_bfloat162*)&u3.y); a3.z += f.x; a3.w += f.y;
    }
    for (; p < e; p++) {
        int n0 = __ldg(nbr + p);
        uint2 u0 = *(const uint2*)(src + (size_t)n0 * DIM + c);
        float2 f;
        f = __bfloat1622float2(*(__nv_bfloat162*)&u0.x); a0.x += f.x; a0.y += f.y;
        f = __bfloat1622float2(*(__nv_bfloat162*)&u0.y); a0.z += f.x; a0.w += f.y;
    }
    float idg = 1.0f / (float)max(e - s, 1);
    a0.x = (a0.x + a1.x + a2.x + a3.x) * idg;
    a0.y = (a0.y + a1.y + a2.y + a3.y) * idg;
    a0.z = (a0.z + a1.z + a2.z + a3.z) * idg;
    a0.w = (a0.w + a1.w + a2.w + a3.w) * idg;
    *(float4*)(dst + (size_t)r * DIM + c) = a0;
}

// ---- merged persistent GEMM+ReLU+LN (unchanged from R7 win) -----------------
__device__ __forceinline__ void load_W_smem(float* Wt, const float* __restrict__ W, int tid) {
    #pragma unroll 4
    for (int it = 0; it < 32; it++) {
        int idx4 = tid + it * 256;          // 8192 float4 of W
        int o  = idx4 & 127;
        int k4 = (idx4 >> 7) << 2;
        float4 w = *(const float4*)(W + o * KDIM + k4);
        Wt[(k4 + 0) * DIM + o] = w.x;
        Wt[(k4 + 1) * DIM + o] = w.y;
        Wt[(k4 + 2) * DIM + o] = w.z;
        Wt[(k4 + 3) * DIM + o] = w.w;
    }
}

__device__ __forceinline__ void do_tile(
    int tile, const float* __restrict__ h, const float* __restrict__ agg,
    float4 bb, float4 gs, float4 gb,
    float* __restrict__ out, int n_rows,
    const float* Wt, float* Xs, int tid)
{
    int row0 = tile * BM;
    #pragma unroll 4
    for (int it = 0; it < 16; it++) {
        int idx4 = tid + it * 256;
        int r  = idx4 >> 6;
        int c4 = (idx4 & 63) << 2;
        int grow = min(row0 + r, n_rows - 1);
        float4 v;
        if (c4 < DIM) v = *(const float4*)(h + (size_t)grow * DIM + c4);
        else          v = *(const float4*)(agg + (size_t)grow * DIM + (c4 - DIM));
        *(float4*)(Xs + r * KDIM + c4) = v;
    }
    __syncthreads();

    int tc = tid & 31;
    int w  = tid >> 5;
    unsigned long long acc[8][2];
    #pragma unroll
    for (int i = 0; i < 8; i++) { acc[i][0] = 0ull; acc[i][1] = 0ull; }
    const float* xbase = Xs + (size_t)(w * 8) * KDIM;

    #pragma unroll 2
    for (int k0 = 0; k0 < KDIM; k0 += 4) {
        const float* wp = Wt + (size_t)k0 * DIM + tc * 4;
        ulonglong2 bq[4];
        #pragma unroll
        for (int kk = 0; kk < 4; kk++)
            bq[kk] = *(const ulonglong2*)(wp + kk * DIM);
        #pragma unroll
        for (int i = 0; i < 8; i++) {
            float4 a = *(const float4*)(xbase + i * KDIM + k0);
            float av[4] = {a.x, a.y, a.z, a.w};
            #pragma unroll
            for (int kk = 0; kk < 4; kk++) {
                unsigned long long aa;
                asm("mov.b64 %0, {%1, %1};" : "=l"(aa) : "f"(av[kk]));
                asm("fma.rn.f32x2 %0, %1, %2, %0;" : "+l"(acc[i][0]) : "l"(aa), "l"(bq[kk].x));
                asm("fma.rn.f32x2 %0, %1, %2, %0;" : "+l"(acc[i][1]) : "l"(aa), "l"(bq[kk].y));
            }
        }
    }

    #pragma unroll
    for (int i = 0; i < 8; i++) {
        int grow = row0 + w * 8 + i;
        float v0, v1, v2, v3;
        asm("mov.b64 {%0, %1}, %2;" : "=f"(v0), "=f"(v1) : "l"(acc[i][0]));
        asm("mov.b64 {%0, %1}, %2;" : "=f"(v2), "=f"(v3) : "l"(acc[i][1]));
        v0 = fmaxf(v0 + bb.x, 0.f);
        v1 = fmaxf(v1 + bb.y, 0.f);
        v2 = fmaxf(v2 + bb.z, 0.f);
        v3 = fmaxf(v3 + bb.w, 0.f);
        float sum = v0 + v1 + v2 + v3;
        float sq  = v0*v0 + v1*v1 + v2*v2 + v3*v3;
        #pragma unroll
        for (int o = 16; o > 0; o >>= 1) {
            sum += __shfl_xor_sync(0xffffffffu, sum, o);
            sq  += __shfl_xor_sync(0xffffffffu, sq,  o);
        }
        float mean = sum * (1.0f / 128.0f);
        float var  = sq * (1.0f / 128.0f) - mean * mean;
        float rstd = rsqrtf(var + LN_EPS);
        if (grow < n_rows) {
            float4 o4;
            o4.x = (v0 - mean) * rstd * gs.x + gb.x;
            o4.y = (v1 - mean) * rstd * gs.y + gb.y;
            o4.z = (v2 - mean) * rstd * gs.z + gb.z;
            o4.w = (v3 - mean) * rstd * gs.w + gb.w;
            *(float4*)(out + (size_t)grow * DIM + tc * 4) = o4;
        }
    }
    __syncthreads();
}

__global__ __launch_bounds__(256, 1) void gemm_ln_kernel(
    const float* __restrict__ job_h, const float* __restrict__ machine_h,
    const float* __restrict__ Wj, const float* __restrict__ bj,
    const float* __restrict__ lnsj, const float* __restrict__ lnbj,
    const float* __restrict__ Wm, const float* __restrict__ bm,
    const float* __restrict__ lnsm, const float* __restrict__ lnbm,
    float* __restrict__ out)
{
    extern __shared__ float smem[];
    float* Wt = smem;                 // 256*128
    float* Xs = smem + KDIM * DIM;    // 64*256
    int tid = threadIdx.x;
    int tc = tid & 31;

    load_W_smem(Wt, Wj, tid);
    __syncthreads();
    {
        float4 bb = *(const float4*)(bj + tc * 4);
        float4 gs = *(const float4*)(lnsj + tc * 4);
        float4 gb = *(const float4*)(lnbj + tc * 4);
        int t = blockIdx.x;
        for (; t < JOB_TILES; t += gridDim.x)
            do_tile(t, job_h, g_job_agg, bb, gs, gb, out, N_JOBS, Wt, Xs, tid);
    }

    __syncthreads();
    load_W_smem(Wt, Wm, tid);
    __syncthreads();
    {
        float4 bb = *(const float4*)(bm + tc * 4);
        float4 gs = *(const float4*)(lnsm + tc * 4);
        float4 gb = *(const float4*)(lnbm + tc * 4);
        int t = blockIdx.x;
        while (t < JOB_TILES) t += gridDim.x;
        for (; t < JOB_TILES + MACH_TILES; t += gridDim.x)
            do_tile(t - JOB_TILES, machine_h, g_mach_agg, bb, gs, gb,
                    out + (size_t)N_JOBS * DIM, N_MACH, Wt, Xs, tid);
    }
}

extern "C" void kernel_launch(void* const* d_in, const int* in_sizes, int n_in,
                              void* d_out, int out_size)
{
    const float* job_h     = (const float*)d_in[0];
    const float* machine_h = (const float*)d_in[1];
    const float* W_job_w   = (const float*)d_in[2];
    const float* W_job_b   = (const float*)d_in[3];
    const float* W_mach_w  = (const float*)d_in[4];
    const float* W_mach_b  = (const float*)d_in[5];
    const float* lnj_s     = (const float*)d_in[6];
    const float* lnj_b     = (const float*)d_in[7];
    const float* lnm_s     = (const float*)d_in[8];
    const float* lnm_b     = (const float*)d_in[9];
    const int*   job_idx   = (const int*)d_in[10];
    const int*   mach_idx  = (const int*)d_in[11];
    float* out = (float*)d_out;
    int n_edges = in_sizes[10];

    const int smem_bytes = (KDIM * DIM + BM * KDIM) * (int)sizeof(float);  // 196608
    cudaFuncSetAttribute(gemm_ln_kernel, cudaFuncAttributeMaxDynamicSharedMemorySize, smem_bytes);

    zero_cnt_kernel<<<128, 256>>>();
    convert_bf16_kernel<<<592, 256>>>(job_h, machine_h);
    hist_kernel<<<592, 256>>>(job_idx, mach_idx, n_edges);
    scanA_kernel<<<JB + MB, 256>>>();
    scanB_kernel<<<1, 256>>>(n_edges);
    scanC_kernel<<<JB + MB, 256>>>();
    fill_kernel<<<592, 256>>>(job_idx, mach_idx, n_edges);

    agg_kernel<<<(int)(((size_t)(N_JOBS + N_MACH) * 32 + 255) / 256), 256>>>();

    gemm_ln_kernel<<<148, 256, smem_bytes>>>(
        job_h, machine_h,
        W_job_w, W_job_b, lnj_s, lnj_b,
        W_mach_w, W_mach_b, lnm_s, lnm_b,
        out);
}